// round 1
// baseline (speedup 1.0000x reference)
#include <cuda_runtime.h>
#include <cuda_bf16.h>
#include <math.h>

#define N_OBJ 2048
#define EMBED 256
#define NH 8
#define NP 32
#define HD 32
#define NUM_IMG 4
#define HH 160
#define WW 160
#define FFN 1024
#define LN_EPS 1e-5f

// ---------------- scratch (device globals; no allocations allowed) ----------
__device__ float g_key_t[(size_t)NUM_IMG * NH * HH * WW * HD]; // (img,h,y,x,d)
__device__ float g_val_t[(size_t)NUM_IMG * NH * HH * WW * HD];
__device__ float g_off[(size_t)N_OBJ * NH * NP * 2];
__device__ float g_x0[(size_t)N_OBJ * EMBED];   // attention output
__device__ float g_x1[(size_t)N_OBJ * EMBED];   // after LN1
__device__ float g_hid[(size_t)N_OBJ * FFN];    // FFN hidden

// ---------------- transpose (img,C,H,W) -> (img,h,y,x,d) --------------------
__global__ void transpose_kv_kernel(const float* __restrict__ key_feat,
                                    const float* __restrict__ value) {
    __shared__ float tile[32][33];
    int x0 = blockIdx.x * 32;
    int y = blockIdx.y;
    int z = blockIdx.z;                 // [0,64): tensor*32 + img*8 + h
    int tensor = z >> 5;
    int rem = z & 31;
    int img = rem >> 3;
    int h = rem & 7;
    const float* src = tensor ? value : key_feat;
    float* dst = tensor ? g_val_t : g_key_t;

    int d = threadIdx.y, tx = threadIdx.x;
    // read: coalesced in x
    tile[d][tx] = src[(((size_t)img * EMBED + h * HD + d) * HH + y) * WW + x0 + tx];
    __syncthreads();
    // write: coalesced in d
    dst[(((size_t)(img * NH + h) * HH + y) * WW + x0 + threadIdx.y) * HD + threadIdx.x]
        = tile[threadIdx.x][threadIdx.y];
}

// ---------------- generic tiled fp32 GEMM with fused epilogues --------------
// C[row, col] = sum_k A[row,k] * W[k,col]  (+bias) (+resid) (relu) (LN)
// block: 256 threads, 32 rows x 256 cols (cols tiled by blockIdx.y).
// LN only valid when NC == 256 and gridDim.y == 1.
#define EP_RELU 1
#define EP_LN 2
#define EP_RESID 4

__global__ void gemm_kernel(const float* __restrict__ A, const float* __restrict__ W,
                            const float* __restrict__ bias, const float* __restrict__ resid,
                            const float* __restrict__ lng, const float* __restrict__ lnb,
                            float* __restrict__ out, int K, int NC, int flags) {
    __shared__ float sA[32 * 64];
    __shared__ float sV[32 * 256];
    __shared__ float sMean[32], sRstd[32];

    int row0 = blockIdx.x * 32;
    int col = blockIdx.y * 256 + threadIdx.x;

    float acc[32];
#pragma unroll
    for (int r = 0; r < 32; r++) acc[r] = 0.f;

    for (int k0 = 0; k0 < K; k0 += 64) {
        __syncthreads();
        for (int i = threadIdx.x; i < 32 * 64; i += 256) {
            int r = i >> 6, c = i & 63;
            sA[i] = A[(size_t)(row0 + r) * K + k0 + c];
        }
        __syncthreads();
#pragma unroll 4
        for (int kk = 0; kk < 64; kk += 4) {
            float w0 = W[(size_t)(k0 + kk + 0) * NC + col];
            float w1 = W[(size_t)(k0 + kk + 1) * NC + col];
            float w2 = W[(size_t)(k0 + kk + 2) * NC + col];
            float w3 = W[(size_t)(k0 + kk + 3) * NC + col];
#pragma unroll
            for (int r = 0; r < 32; r++) {
                float4 a4 = *reinterpret_cast<const float4*>(&sA[r * 64 + kk]);
                acc[r] = fmaf(a4.x, w0, acc[r]);
                acc[r] = fmaf(a4.y, w1, acc[r]);
                acc[r] = fmaf(a4.z, w2, acc[r]);
                acc[r] = fmaf(a4.w, w3, acc[r]);
            }
        }
    }

    float bv = bias ? bias[col] : 0.f;
#pragma unroll
    for (int r = 0; r < 32; r++) {
        float v = acc[r] + bv;
        if (flags & EP_RESID) v += resid[(size_t)(row0 + r) * NC + col];
        if (flags & EP_RELU) v = fmaxf(v, 0.f);
        acc[r] = v;
    }

    if (flags & EP_LN) {
#pragma unroll
        for (int r = 0; r < 32; r++) sV[r * 256 + threadIdx.x] = acc[r];
        __syncthreads();
        int warp = threadIdx.x >> 5, lane = threadIdx.x & 31;
        for (int r = warp * 4; r < warp * 4 + 4; r++) {
            float s = 0.f, s2 = 0.f;
#pragma unroll
            for (int j = 0; j < 8; j++) {
                float x = sV[r * 256 + lane + 32 * j];
                s += x;
                s2 += x * x;
            }
            for (int o = 16; o > 0; o >>= 1) {
                s += __shfl_xor_sync(0xffffffffu, s, o);
                s2 += __shfl_xor_sync(0xffffffffu, s2, o);
            }
            if (lane == 0) {
                float m = s * (1.f / 256.f);
                float var = s2 * (1.f / 256.f) - m * m;
                sMean[r] = m;
                sRstd[r] = rsqrtf(var + LN_EPS);
            }
        }
        __syncthreads();
        float g = lng[col], b = lnb[col];
#pragma unroll
        for (int r = 0; r < 32; r++) {
            float v = (acc[r] - sMean[r]) * sRstd[r] * g + b;
            out[(size_t)(row0 + r) * NC + col] = v;
        }
    } else {
#pragma unroll
        for (int r = 0; r < 32; r++)
            out[(size_t)(row0 + r) * NC + col] = acc[r];
    }
}

// ---------------- sampler: bilinear gather + attention ----------------------
// 1 block / object, warp w -> head w, lane -> channel d (and later point p).
__global__ void sampler_kernel(const float* __restrict__ query,
                               const float* __restrict__ obj_xy,
                               const float* __restrict__ strides,
                               const int* __restrict__ img_ind,
                               const float* __restrict__ x2d,
                               const float* __restrict__ x2d_mask,
                               float* __restrict__ v_samples,
                               float* __restrict__ a_samples,
                               float* __restrict__ mask_samples,
                               float* __restrict__ x2d_samples,
                               float* __restrict__ x0_out) {
    __shared__ float sV[NH * NP * 33];
    int n = blockIdx.x;
    int warp = threadIdx.x >> 5, lane = threadIdx.x & 31;
    int h = warp;

    int img = img_ind[n];
    float px = obj_xy[n * 2 + 0];
    float py = obj_xy[n * 2 + 1];
    float st = strides[n];
    float qd = query[(size_t)n * EMBED + h * HD + lane];

    const float* kbase = g_key_t + (size_t)(img * NH + h) * HH * WW * HD;
    const float* vbase = g_val_t + (size_t)(img * NH + h) * HH * WW * HD;
    const float* x2d0 = x2d + (size_t)(img * 2 + 0) * HH * WW;
    const float* x2d1 = x2d + (size_t)(img * 2 + 1) * HH * WW;
    const float* mbase = x2d_mask + (size_t)img * HH * WW;

    float a_reg = 0.f, mask_reg = 0.f, xa_reg = 0.f, xb_reg = 0.f;

    for (int p = 0; p < NP; p++) {
        float ox = g_off[(size_t)n * 512 + h * 64 + p * 2 + 0];
        float oy = g_off[(size_t)n * 512 + h * 64 + p * 2 + 1];
        float lx = px + ox * st;
        float ly = py + oy * st;
        float gx = lx * (2.f / 640.f) - 1.f;
        float gy = ly * (2.f / 640.f) - 1.f;
        float ix = ((gx + 1.f) * (float)WW - 1.f) * 0.5f;
        float iy = ((gy + 1.f) * (float)HH - 1.f) * 0.5f;
        float x0f = floorf(ix), y0f = floorf(iy);
        float wx1 = ix - x0f, wy1 = iy - y0f;
        int x0 = (int)x0f, y0 = (int)y0f;

        float ks = 0.f, vs = 0.f, ms = 0.f, xa = 0.f, xb = 0.f;
#pragma unroll
        for (int c = 0; c < 4; c++) {
            int dx = c & 1, dy = c >> 1;
            float wgt = (dx ? wx1 : 1.f - wx1) * (dy ? wy1 : 1.f - wy1);
            int xi = x0 + dx, yi = y0 + dy;
            int xc = min(max(xi, 0), WW - 1);
            int yc = min(max(yi, 0), HH - 1);
            int pix = yc * WW + xc;
            size_t base = (size_t)pix * HD + lane;
            ks = fmaf(kbase[base], wgt, ks);
            vs = fmaf(vbase[base], wgt, vs);
            xa = fmaf(x2d0[pix], wgt, xa);
            xb = fmaf(x2d1[pix], wgt, xb);
            bool valid = (xi >= 0) && (xi < WW) && (yi >= 0) && (yi < HH);
            if (valid) ms = fmaf(mbase[pix], wgt, ms);
        }
        sV[(h * NP + p) * 33 + lane] = vs;

        float prt = qd * ks;
        for (int o = 16; o > 0; o >>= 1) prt += __shfl_xor_sync(0xffffffffu, prt, o);
        float a = prt * 0.17677669529663687f;  // 1/sqrt(32)

        if (lane == p) {
            a_reg = a;
            mask_reg = ms;
            xa_reg = xa;
            xb_reg = xb;
        }
    }
    __syncwarp();

    // sample outputs (lane == point index p)
    size_t sbase = (size_t)(n * NH + h) * NP + lane;
    a_samples[sbase] = a_reg;
    mask_samples[sbase] = mask_reg;
    x2d_samples[(size_t)((n * NH + h) * 2 + 0) * NP + lane] = xa_reg;
    x2d_samples[(size_t)((n * NH + h) * 2 + 1) * NP + lane] = xb_reg;
    // v_samples: (n, h, d, p) — lane = p, loop over d, coalesced over p
#pragma unroll 4
    for (int d = 0; d < HD; d++)
        v_samples[(size_t)((n * NH + h) * HD + d) * NP + lane] = sV[(h * NP + lane) * 33 + d];

    // softmax over points (lane = p)
    float m = a_reg;
    for (int o = 16; o > 0; o >>= 1) m = fmaxf(m, __shfl_xor_sync(0xffffffffu, m, o));
    float e = expf(a_reg - m);
    float s = e;
    for (int o = 16; o > 0; o >>= 1) s += __shfl_xor_sync(0xffffffffu, s, o);
    float a_sm = e / s * mask_reg;

    // out[h][d] = sum_p v_s[p][d] * a_sm[p]   (lane = d again)
    float acc = 0.f;
#pragma unroll
    for (int p = 0; p < NP; p++) {
        float w = __shfl_sync(0xffffffffu, a_sm, p);
        acc = fmaf(sV[(h * NP + p) * 33 + lane], w, acc);
    }
    x0_out[(size_t)n * EMBED + h * HD + lane] = acc;
}

// ---------------- launch ----------------------------------------------------
extern "C" void kernel_launch(void* const* d_in, const int* in_sizes, int n_in,
                              void* d_out, int out_size) {
    const float* query    = (const float*)d_in[0];
    const float* obj_emb  = (const float*)d_in[1];
    const float* key_feat = (const float*)d_in[2];
    const float* value    = (const float*)d_in[3];
    const float* x2d      = (const float*)d_in[4];
    const float* x2d_mask = (const float*)d_in[5];
    const float* obj_xy   = (const float*)d_in[6];
    const float* strides  = (const float*)d_in[7];
    const int*   img_ind  = (const int*)d_in[8];
    const float* w_off    = (const float*)d_in[9];
    const float* b_off    = (const float*)d_in[10];
    const float* w_out    = (const float*)d_in[11];
    const float* b_out    = (const float*)d_in[12];
    const float* ln1_g    = (const float*)d_in[13];
    const float* ln1_b    = (const float*)d_in[14];
    const float* w1       = (const float*)d_in[15];
    const float* b1       = (const float*)d_in[16];
    const float* w2       = (const float*)d_in[17];
    const float* b2       = (const float*)d_in[18];
    const float* ln2_g    = (const float*)d_in[19];
    const float* ln2_b    = (const float*)d_in[20];

    float* out = (float*)d_out;
    // output layout: [out(2048,256)][v_samples(2048,8,32,32)][a(2048,8,1,32)]
    //                [mask(2048,8,1,32)][x2d(2048,8,2,32)]
    float* out_main = out;
    float* out_v    = out + (size_t)N_OBJ * EMBED;
    float* out_a    = out_v + (size_t)N_OBJ * NH * HD * NP;
    float* out_m    = out_a + (size_t)N_OBJ * NH * NP;
    float* out_x2d  = out_m + (size_t)N_OBJ * NH * NP;

    float *p_off, *p_x0, *p_x1, *p_hid;
    cudaGetSymbolAddress((void**)&p_off, g_off);
    cudaGetSymbolAddress((void**)&p_x0, g_x0);
    cudaGetSymbolAddress((void**)&p_x1, g_x1);
    cudaGetSymbolAddress((void**)&p_hid, g_hid);

    // 1) transpose K/V to (img,h,y,x,d)
    transpose_kv_kernel<<<dim3(WW / 32, HH, 2 * NUM_IMG * NH), dim3(32, 32)>>>(key_feat, value);

    // 2) offsets = obj_emb @ w_off + b_off   (2048x512, K=256)
    gemm_kernel<<<dim3(N_OBJ / 32, 2), 256>>>(obj_emb, w_off, b_off, nullptr, nullptr, nullptr,
                                              p_off, EMBED, NH * NP * 2, 0);

    // 3) sampler (bilinear gather + attention + sample outputs)
    sampler_kernel<<<N_OBJ, 256>>>(query, obj_xy, strides, img_ind, x2d, x2d_mask,
                                   out_v, out_a, out_m, out_x2d, p_x0);

    // 4) x1 = LN1(x0 @ w_out + b_out + obj_emb)
    gemm_kernel<<<dim3(N_OBJ / 32, 1), 256>>>(p_x0, w_out, b_out, obj_emb, ln1_g, ln1_b,
                                              p_x1, EMBED, EMBED, EP_RESID | EP_LN);

    // 5) hid = relu(x1 @ w1 + b1)   (2048x1024, K=256)
    gemm_kernel<<<dim3(N_OBJ / 32, 4), 256>>>(p_x1, w1, b1, nullptr, nullptr, nullptr,
                                              p_hid, EMBED, FFN, EP_RELU);

    // 6) out = LN2(hid @ w2 + b2 + x1)   (2048x256, K=1024)
    gemm_kernel<<<dim3(N_OBJ / 32, 1), 256>>>(p_hid, w2, b2, p_x1, ln2_g, ln2_b,
                                              out_main, FFN, EMBED, EP_RESID | EP_LN);
}

// round 2
// speedup vs baseline: 1.5240x; 1.5240x over previous
#include <cuda_runtime.h>
#include <cuda_bf16.h>
#include <math.h>

#define N_OBJ 2048
#define EMBED 256
#define NH 8
#define NP 32
#define HD 32
#define NUM_IMG 4
#define HH 160
#define WW 160
#define FFN 1024
#define LN_EPS 1e-5f

// ---------------- scratch (device globals; no allocations allowed) ----------
__device__ float g_key_t[(size_t)NUM_IMG * NH * HH * WW * HD]; // (img,h,y,x,d)
__device__ float g_val_t[(size_t)NUM_IMG * NH * HH * WW * HD];
__device__ float g_off[(size_t)N_OBJ * NH * NP * 2];
__device__ float g_x0[(size_t)N_OBJ * EMBED];   // attention output
__device__ float g_x1[(size_t)N_OBJ * EMBED];   // after LN1
__device__ float g_hid[(size_t)N_OBJ * FFN];    // FFN hidden

// ---------------- transpose (img,C,H,W) -> (img,h,y,x,d) --------------------
__global__ void transpose_kv_kernel(const float* __restrict__ key_feat,
                                    const float* __restrict__ value) {
    __shared__ float tile[32][33];
    int x0 = blockIdx.x * 32;
    int y = blockIdx.y;
    int z = blockIdx.z;                 // [0,64): tensor*32 + img*8 + h
    int tensor = z >> 5;
    int rem = z & 31;
    int img = rem >> 3;
    int h = rem & 7;
    const float* src = tensor ? value : key_feat;
    float* dst = tensor ? g_val_t : g_key_t;

    int d = threadIdx.y, tx = threadIdx.x;
    tile[d][tx] = src[(((size_t)img * EMBED + h * HD + d) * HH + y) * WW + x0 + tx];
    __syncthreads();
    dst[(((size_t)(img * NH + h) * HH + y) * WW + x0 + threadIdx.y) * HD + threadIdx.x]
        = tile[threadIdx.x][threadIdx.y];
}

// ---------------- 64x64 tiled fp32 GEMM, 128 threads, 8x4 per thread --------
#define EP_RELU 1
#define EP_RESID 2

__global__ __launch_bounds__(128)
void gemm64_kernel(const float* __restrict__ A, const float* __restrict__ W,
                   const float* __restrict__ bias, const float* __restrict__ resid,
                   float* __restrict__ out, int K, int NC, int flags) {
    __shared__ float sA[16][68];   // [k][row]
    __shared__ float sW[16][68];   // [k][col]
    int tid = threadIdx.x;
    int tx = tid & 15;             // col group (0..15) -> 4 cols
    int ty = tid >> 4;             // row group (0..7)  -> 8 rows
    int row0 = blockIdx.x * 64;
    int col0 = blockIdx.y * 64;

    float acc[8][4];
#pragma unroll
    for (int i = 0; i < 8; i++)
#pragma unroll
        for (int j = 0; j < 4; j++) acc[i][j] = 0.f;

    for (int k0 = 0; k0 < K; k0 += 16) {
#pragma unroll
        for (int l = 0; l < 2; l++) {
            int i = tid + l * 128;
            // A: 64 rows x 16 k = 256 float4 slots
            int r  = i >> 2;
            int ak = (i & 3) * 4;
            float4 a = *reinterpret_cast<const float4*>(&A[(size_t)(row0 + r) * K + k0 + ak]);
            sA[ak + 0][r] = a.x; sA[ak + 1][r] = a.y;
            sA[ak + 2][r] = a.z; sA[ak + 3][r] = a.w;
            // W: 16 k x 64 cols = 256 float4 slots
            int wk = i >> 4;
            int wc = (i & 15) * 4;
            *reinterpret_cast<float4*>(&sW[wk][wc]) =
                *reinterpret_cast<const float4*>(&W[(size_t)(k0 + wk) * NC + col0 + wc]);
        }
        __syncthreads();
#pragma unroll
        for (int kk = 0; kk < 16; kk++) {
            float4 w4 = *reinterpret_cast<float4*>(&sW[kk][tx * 4]);
            float4 al = *reinterpret_cast<float4*>(&sA[kk][ty * 8]);
            float4 ah = *reinterpret_cast<float4*>(&sA[kk][ty * 8 + 4]);
            float av[8] = {al.x, al.y, al.z, al.w, ah.x, ah.y, ah.z, ah.w};
            float wv[4] = {w4.x, w4.y, w4.z, w4.w};
#pragma unroll
            for (int i = 0; i < 8; i++)
#pragma unroll
                for (int j = 0; j < 4; j++)
                    acc[i][j] = fmaf(av[i], wv[j], acc[i][j]);
        }
        __syncthreads();
    }

    float4 bv = make_float4(0.f, 0.f, 0.f, 0.f);
    if (bias) bv = *reinterpret_cast<const float4*>(&bias[col0 + tx * 4]);
#pragma unroll
    for (int i = 0; i < 8; i++) {
        int row = row0 + ty * 8 + i;
        float4 o;
        o.x = acc[i][0] + bv.x; o.y = acc[i][1] + bv.y;
        o.z = acc[i][2] + bv.z; o.w = acc[i][3] + bv.w;
        if (flags & EP_RESID) {
            float4 rv = *reinterpret_cast<const float4*>(&resid[(size_t)row * NC + col0 + tx * 4]);
            o.x += rv.x; o.y += rv.y; o.z += rv.z; o.w += rv.w;
        }
        if (flags & EP_RELU) {
            o.x = fmaxf(o.x, 0.f); o.y = fmaxf(o.y, 0.f);
            o.z = fmaxf(o.z, 0.f); o.w = fmaxf(o.w, 0.f);
        }
        *reinterpret_cast<float4*>(&out[(size_t)row * NC + col0 + tx * 4]) = o;
    }
}

// ---------------- in-place LayerNorm over 256 cols, warp per row ------------
__global__ void ln_kernel(float* __restrict__ x, const float* __restrict__ g,
                          const float* __restrict__ b) {
    int row = blockIdx.x * 8 + (threadIdx.x >> 5);
    int lane = threadIdx.x & 31;
    float v[8];
    float s = 0.f, s2 = 0.f;
#pragma unroll
    for (int j = 0; j < 8; j++) {
        v[j] = x[(size_t)row * 256 + lane + 32 * j];
        s += v[j];
        s2 += v[j] * v[j];
    }
#pragma unroll
    for (int o = 16; o > 0; o >>= 1) {
        s += __shfl_xor_sync(0xffffffffu, s, o);
        s2 += __shfl_xor_sync(0xffffffffu, s2, o);
    }
    float m = s * (1.f / 256.f);
    float r = rsqrtf(s2 * (1.f / 256.f) - m * m + LN_EPS);
#pragma unroll
    for (int j = 0; j < 8; j++)
        x[(size_t)row * 256 + lane + 32 * j] =
            (v[j] - m) * r * g[lane + 32 * j] + b[lane + 32 * j];
}

// ---------------- sampler: bilinear gather + attention ----------------------
__global__ __launch_bounds__(256)
void sampler_kernel(const float* __restrict__ query,
                    const float* __restrict__ obj_xy,
                    const float* __restrict__ strides,
                    const int* __restrict__ img_ind,
                    const float* __restrict__ x2d,
                    const float* __restrict__ x2d_mask,
                    float* __restrict__ v_samples,
                    float* __restrict__ a_samples,
                    float* __restrict__ mask_samples,
                    float* __restrict__ x2d_samples,
                    float* __restrict__ x0_out) {
    __shared__ float sV[NH * NP * 33];
    int n = blockIdx.x;
    int h = threadIdx.x >> 5, lane = threadIdx.x & 31;

    int img = img_ind[n];
    float px = obj_xy[n * 2 + 0];
    float py = obj_xy[n * 2 + 1];
    float st = strides[n];
    float qd = query[(size_t)n * EMBED + h * HD + lane];

    const float* kbase = g_key_t + (size_t)(img * NH + h) * HH * WW * HD;
    const float* vbase = g_val_t + (size_t)(img * NH + h) * HH * WW * HD;
    const float* x2d0 = x2d + (size_t)(img * 2 + 0) * HH * WW;
    const float* x2d1 = x2d + (size_t)(img * 2 + 1) * HH * WW;
    const float* mbase = x2d_mask + (size_t)img * HH * WW;

    // ---- per-lane point setup: lane == point p ----
    size_t obase = (size_t)n * 512 + h * 64;
    float ox = g_off[obase + lane * 2 + 0];
    float oy = g_off[obase + lane * 2 + 1];
    // ix = lx*0.25 - 0.5 (W==H==160, STRIDE==4)
    float ixl = fmaf(px + ox * st, 0.25f, -0.5f);
    float iyl = fmaf(py + oy * st, 0.25f, -0.5f);
    float x0f = floorf(ixl), y0f = floorf(iyl);
    float wx1 = ixl - x0f, wy1 = iyl - y0f;
    int x0 = (int)x0f, y0 = (int)y0f;

    // per-lane x2d / mask bilinear (scalar arrays)
    float xa_reg = 0.f, xb_reg = 0.f, mask_reg = 0.f;
#pragma unroll
    for (int c = 0; c < 4; c++) {
        int dx = c & 1, dy = c >> 1;
        float wgt = (dx ? wx1 : 1.f - wx1) * (dy ? wy1 : 1.f - wy1);
        int xi = x0 + dx, yi = y0 + dy;
        int xc = min(max(xi, 0), WW - 1);
        int yc = min(max(yi, 0), HH - 1);
        int pix = yc * WW + xc;
        xa_reg = fmaf(__ldg(&x2d0[pix]), wgt, xa_reg);
        xb_reg = fmaf(__ldg(&x2d1[pix]), wgt, xb_reg);
        bool valid = (xi >= 0) && (xi < WW) && (yi >= 0) && (yi < HH);
        if (valid) mask_reg = fmaf(__ldg(&mbase[pix]), wgt, mask_reg);
    }

    // ---- K/V gather + logits, 2 points per iteration ----
    float a_reg = 0.f;
    const float ascale = 0.17677669529663687f; // 1/sqrt(32)
#pragma unroll
    for (int p = 0; p < NP; p += 2) {
        int xA = __shfl_sync(0xffffffffu, x0, p);
        int yA = __shfl_sync(0xffffffffu, y0, p);
        float wxA = __shfl_sync(0xffffffffu, wx1, p);
        float wyA = __shfl_sync(0xffffffffu, wy1, p);
        int xB = __shfl_sync(0xffffffffu, x0, p + 1);
        int yB = __shfl_sync(0xffffffffu, y0, p + 1);
        float wxB = __shfl_sync(0xffffffffu, wx1, p + 1);
        float wyB = __shfl_sync(0xffffffffu, wy1, p + 1);

        float ksA = 0.f, vsA = 0.f, ksB = 0.f, vsB = 0.f;
#pragma unroll
        for (int c = 0; c < 4; c++) {
            int dx = c & 1, dy = c >> 1;
            float wgtA = (dx ? wxA : 1.f - wxA) * (dy ? wyA : 1.f - wyA);
            float wgtB = (dx ? wxB : 1.f - wxB) * (dy ? wyB : 1.f - wyB);
            int pixA = min(max(yA + dy, 0), HH - 1) * WW + min(max(xA + dx, 0), WW - 1);
            int pixB = min(max(yB + dy, 0), HH - 1) * WW + min(max(xB + dx, 0), WW - 1);
            float kA = kbase[(size_t)pixA * HD + lane];
            float vA = vbase[(size_t)pixA * HD + lane];
            float kB = kbase[(size_t)pixB * HD + lane];
            float vB = vbase[(size_t)pixB * HD + lane];
            ksA = fmaf(kA, wgtA, ksA);
            vsA = fmaf(vA, wgtA, vsA);
            ksB = fmaf(kB, wgtB, ksB);
            vsB = fmaf(vB, wgtB, vsB);
        }
        sV[(h * NP + p) * 33 + lane] = vsA;
        sV[(h * NP + p + 1) * 33 + lane] = vsB;

        float prtA = qd * ksA;
        float prtB = qd * ksB;
#pragma unroll
        for (int o = 16; o > 0; o >>= 1) {
            prtA += __shfl_xor_sync(0xffffffffu, prtA, o);
            prtB += __shfl_xor_sync(0xffffffffu, prtB, o);
        }
        if (lane == p) a_reg = prtA * ascale;
        if (lane == p + 1) a_reg = prtB * ascale;
    }
    __syncwarp();

    // ---- sample outputs (lane == point index p) ----
    size_t sbase = (size_t)(n * NH + h) * NP + lane;
    a_samples[sbase] = a_reg;
    mask_samples[sbase] = mask_reg;
    x2d_samples[(size_t)((n * NH + h) * 2 + 0) * NP + lane] = xa_reg;
    x2d_samples[(size_t)((n * NH + h) * 2 + 1) * NP + lane] = xb_reg;
#pragma unroll 4
    for (int d = 0; d < HD; d++)
        v_samples[(size_t)((n * NH + h) * HD + d) * NP + lane] = sV[(h * NP + lane) * 33 + d];

    // ---- softmax over points (lane = p) ----
    float m = a_reg;
#pragma unroll
    for (int o = 16; o > 0; o >>= 1) m = fmaxf(m, __shfl_xor_sync(0xffffffffu, m, o));
    float e = expf(a_reg - m);
    float s = e;
#pragma unroll
    for (int o = 16; o > 0; o >>= 1) s += __shfl_xor_sync(0xffffffffu, s, o);
    float a_sm = e / s * mask_reg;

    // ---- out[h][d] = sum_p v_s[p][d] * a_sm[p]  (lane = d) ----
    float acc = 0.f;
#pragma unroll
    for (int p = 0; p < NP; p++) {
        float w = __shfl_sync(0xffffffffu, a_sm, p);
        acc = fmaf(sV[(h * NP + p) * 33 + lane], w, acc);
    }
    x0_out[(size_t)n * EMBED + h * HD + lane] = acc;
}

// ---------------- launch ----------------------------------------------------
extern "C" void kernel_launch(void* const* d_in, const int* in_sizes, int n_in,
                              void* d_out, int out_size) {
    const float* query    = (const float*)d_in[0];
    const float* obj_emb  = (const float*)d_in[1];
    const float* key_feat = (const float*)d_in[2];
    const float* value    = (const float*)d_in[3];
    const float* x2d      = (const float*)d_in[4];
    const float* x2d_mask = (const float*)d_in[5];
    const float* obj_xy   = (const float*)d_in[6];
    const float* strides  = (const float*)d_in[7];
    const int*   img_ind  = (const int*)d_in[8];
    const float* w_off    = (const float*)d_in[9];
    const float* b_off    = (const float*)d_in[10];
    const float* w_out    = (const float*)d_in[11];
    const float* b_out    = (const float*)d_in[12];
    const float* ln1_g    = (const float*)d_in[13];
    const float* ln1_b    = (const float*)d_in[14];
    const float* w1       = (const float*)d_in[15];
    const float* b1       = (const float*)d_in[16];
    const float* w2       = (const float*)d_in[17];
    const float* b2       = (const float*)d_in[18];
    const float* ln2_g    = (const float*)d_in[19];
    const float* ln2_b    = (const float*)d_in[20];

    float* out = (float*)d_out;
    float* out_main = out;
    float* out_v    = out + (size_t)N_OBJ * EMBED;
    float* out_a    = out_v + (size_t)N_OBJ * NH * HD * NP;
    float* out_m    = out_a + (size_t)N_OBJ * NH * NP;
    float* out_x2d  = out_m + (size_t)N_OBJ * NH * NP;

    float *p_off, *p_x0, *p_x1, *p_hid;
    cudaGetSymbolAddress((void**)&p_off, g_off);
    cudaGetSymbolAddress((void**)&p_x0, g_x0);
    cudaGetSymbolAddress((void**)&p_x1, g_x1);
    cudaGetSymbolAddress((void**)&p_hid, g_hid);

    // 1) transpose K/V to (img,h,y,x,d)
    transpose_kv_kernel<<<dim3(WW / 32, HH, 2 * NUM_IMG * NH), dim3(32, 32)>>>(key_feat, value);

    // 2) offsets = obj_emb @ w_off + b_off   (2048x512, K=256)
    gemm64_kernel<<<dim3(N_OBJ / 64, 8), 128>>>(obj_emb, w_off, b_off, nullptr,
                                                p_off, EMBED, NH * NP * 2, 0);

    // 3) sampler
    sampler_kernel<<<N_OBJ, 256>>>(query, obj_xy, strides, img_ind, x2d, x2d_mask,
                                   out_v, out_a, out_m, out_x2d, p_x0);

    // 4) x1 = LN1(x0 @ w_out + b_out + obj_emb)
    gemm64_kernel<<<dim3(N_OBJ / 64, 4), 128>>>(p_x0, w_out, b_out, obj_emb,
                                                p_x1, EMBED, EMBED, EP_RESID);
    ln_kernel<<<N_OBJ / 8, 256>>>(p_x1, ln1_g, ln1_b);

    // 5) hid = relu(x1 @ w1 + b1)
    gemm64_kernel<<<dim3(N_OBJ / 64, 16), 128>>>(p_x1, w1, b1, nullptr,
                                                 p_hid, EMBED, FFN, EP_RELU);

    // 6) out = LN2(hid @ w2 + b2 + x1)
    gemm64_kernel<<<dim3(N_OBJ / 64, 4), 128>>>(p_hid, w2, b2, p_x1,
                                                out_main, FFN, EMBED, EP_RESID);
    ln_kernel<<<N_OBJ / 8, 256>>>(out_main, ln2_g, ln2_b);
}

// round 3
// speedup vs baseline: 1.6426x; 1.0778x over previous
#include <cuda_runtime.h>
#include <cuda_bf16.h>
#include <math.h>

#define N_OBJ 2048
#define EMBED 256
#define NH 8
#define NP 32
#define HD 32
#define NUM_IMG 4
#define HH 160
#define WW 160
#define FFN 1024
#define LN_EPS 1e-5f

// ---------------- scratch (device globals; no allocations allowed) ----------
__device__ float g_key_t[(size_t)NUM_IMG * NH * HH * WW * HD]; // (img,h,y,x,d)
__device__ float g_val_t[(size_t)NUM_IMG * NH * HH * WW * HD];
__device__ float g_off[(size_t)N_OBJ * NH * NP * 2];
__device__ float g_x0[(size_t)N_OBJ * EMBED];
__device__ float g_x1[(size_t)N_OBJ * EMBED];
__device__ float g_hid[(size_t)N_OBJ * FFN];

// ---------------- transpose (img,C,H,W) -> (img,h,y,x,d) --------------------
__global__ void transpose_kv_kernel(const float* __restrict__ key_feat,
                                    const float* __restrict__ value) {
    __shared__ float tile[32][33];
    int x0 = blockIdx.x * 32;
    int y = blockIdx.y;
    int z = blockIdx.z;                 // [0,64): tensor*32 + img*8 + h
    int tensor = z >> 5;
    int rem = z & 31;
    int img = rem >> 3;
    int h = rem & 7;
    const float* src = tensor ? value : key_feat;
    float* dst = tensor ? g_val_t : g_key_t;

    tile[threadIdx.y][threadIdx.x] =
        src[(((size_t)img * EMBED + h * HD + threadIdx.y) * HH + y) * WW + x0 + threadIdx.x];
    __syncthreads();
    dst[(((size_t)(img * NH + h) * HH + y) * WW + x0 + threadIdx.y) * HD + threadIdx.x]
        = tile[threadIdx.x][threadIdx.y];
}

// ---------------- tiled fp32 GEMM (BM x 64), 128 threads, reg-staged --------
#define EP_RELU 1
#define EP_RESID 2

template <int BM>
__global__ __launch_bounds__(128)
void gemm_kernel(const float* __restrict__ A, const float* __restrict__ W,
                 const float* __restrict__ bias, const float* __restrict__ resid,
                 float* __restrict__ out, int K, int NC, int flags) {
    constexpr int RPT = BM / 8;       // rows per thread
    constexpr int ANUM = BM / 32;     // A float4 loads per thread
    __shared__ float sA[16][BM + 4];  // [k][row]
    __shared__ float sW[16][68];      // [k][col]
    int tid = threadIdx.x;
    int tx = tid & 15;                // 4 cols
    int ty = tid >> 4;                // RPT rows
    int row0 = blockIdx.x * BM;
    int col0 = blockIdx.y * 64;

    float acc[RPT][4];
#pragma unroll
    for (int i = 0; i < RPT; i++)
#pragma unroll
        for (int j = 0; j < 4; j++) acc[i][j] = 0.f;

    float4 ra[ANUM], rw[2];
#pragma unroll
    for (int l = 0; l < ANUM; l++) {
        int i = tid + l * 128;
        ra[l] = *reinterpret_cast<const float4*>(&A[(size_t)(row0 + (i >> 2)) * K + (i & 3) * 4]);
    }
#pragma unroll
    for (int l = 0; l < 2; l++) {
        int i = tid + l * 128;
        rw[l] = *reinterpret_cast<const float4*>(&W[(size_t)(i >> 4) * NC + col0 + (i & 15) * 4]);
    }

    for (int k0 = 0; k0 < K; k0 += 16) {
#pragma unroll
        for (int l = 0; l < ANUM; l++) {
            int i = tid + l * 128;
            int r = i >> 2, ak = (i & 3) * 4;
            sA[ak + 0][r] = ra[l].x; sA[ak + 1][r] = ra[l].y;
            sA[ak + 2][r] = ra[l].z; sA[ak + 3][r] = ra[l].w;
        }
#pragma unroll
        for (int l = 0; l < 2; l++) {
            int i = tid + l * 128;
            *reinterpret_cast<float4*>(&sW[i >> 4][(i & 15) * 4]) = rw[l];
        }
        __syncthreads();
        if (k0 + 16 < K) {
#pragma unroll
            for (int l = 0; l < ANUM; l++) {
                int i = tid + l * 128;
                ra[l] = *reinterpret_cast<const float4*>(
                    &A[(size_t)(row0 + (i >> 2)) * K + k0 + 16 + (i & 3) * 4]);
            }
#pragma unroll
            for (int l = 0; l < 2; l++) {
                int i = tid + l * 128;
                rw[l] = *reinterpret_cast<const float4*>(
                    &W[(size_t)(k0 + 16 + (i >> 4)) * NC + col0 + (i & 15) * 4]);
            }
        }
#pragma unroll
        for (int kk = 0; kk < 16; kk++) {
            float4 w4 = *reinterpret_cast<float4*>(&sW[kk][tx * 4]);
            float wv[4] = {w4.x, w4.y, w4.z, w4.w};
            float av[RPT];
#pragma unroll
            for (int l = 0; l < RPT / 4; l++) {
                float4 a4 = *reinterpret_cast<float4*>(&sA[kk][ty * RPT + l * 4]);
                av[l * 4 + 0] = a4.x; av[l * 4 + 1] = a4.y;
                av[l * 4 + 2] = a4.z; av[l * 4 + 3] = a4.w;
            }
#pragma unroll
            for (int i = 0; i < RPT; i++)
#pragma unroll
                for (int j = 0; j < 4; j++)
                    acc[i][j] = fmaf(av[i], wv[j], acc[i][j]);
        }
        __syncthreads();
    }

    float4 bv = make_float4(0.f, 0.f, 0.f, 0.f);
    if (bias) bv = *reinterpret_cast<const float4*>(&bias[col0 + tx * 4]);
#pragma unroll
    for (int i = 0; i < RPT; i++) {
        int row = row0 + ty * RPT + i;
        float4 o;
        o.x = acc[i][0] + bv.x; o.y = acc[i][1] + bv.y;
        o.z = acc[i][2] + bv.z; o.w = acc[i][3] + bv.w;
        if (flags & EP_RESID) {
            float4 rv = *reinterpret_cast<const float4*>(&resid[(size_t)row * NC + col0 + tx * 4]);
            o.x += rv.x; o.y += rv.y; o.z += rv.z; o.w += rv.w;
        }
        if (flags & EP_RELU) {
            o.x = fmaxf(o.x, 0.f); o.y = fmaxf(o.y, 0.f);
            o.z = fmaxf(o.z, 0.f); o.w = fmaxf(o.w, 0.f);
        }
        *reinterpret_cast<float4*>(&out[(size_t)row * NC + col0 + tx * 4]) = o;
    }
}

// ---------------- in-place LayerNorm over 256 cols, warp per row ------------
__global__ void ln_kernel(float* __restrict__ x, const float* __restrict__ g,
                          const float* __restrict__ b) {
    int row = blockIdx.x * 8 + (threadIdx.x >> 5);
    int lane = threadIdx.x & 31;
    float v[8];
    float s = 0.f, s2 = 0.f;
#pragma unroll
    for (int j = 0; j < 8; j++) {
        v[j] = x[(size_t)row * 256 + lane + 32 * j];
        s += v[j];
        s2 += v[j] * v[j];
    }
#pragma unroll
    for (int o = 16; o > 0; o >>= 1) {
        s += __shfl_xor_sync(0xffffffffu, s, o);
        s2 += __shfl_xor_sync(0xffffffffu, s2, o);
    }
    float m = s * (1.f / 256.f);
    float r = rsqrtf(s2 * (1.f / 256.f) - m * m + LN_EPS);
#pragma unroll
    for (int j = 0; j < 8; j++)
        x[(size_t)row * 256 + lane + 32 * j] =
            (v[j] - m) * r * g[lane + 32 * j] + b[lane + 32 * j];
}

// ---------------- sampler: 1024 thr/object, warp = (head, point-octet) ------
__global__ __launch_bounds__(1024)
void sampler_kernel(const float* __restrict__ query,
                    const float* __restrict__ obj_xy,
                    const float* __restrict__ strides,
                    const int* __restrict__ img_ind,
                    const float* __restrict__ x2d,
                    const float* __restrict__ x2d_mask,
                    float* __restrict__ v_samples,
                    float* __restrict__ a_samples,
                    float* __restrict__ mask_samples,
                    float* __restrict__ x2d_samples,
                    float* __restrict__ x0_out) {
    __shared__ float sV[NH][NP][HD + 1];
    __shared__ float sA[NH][NP];
    __shared__ float sMask[NH][NP];
    __shared__ float sXa[NH][NP];
    __shared__ float sXb[NH][NP];
    __shared__ float sSm[NH][NP];

    int n = blockIdx.x;
    int w = threadIdx.x >> 5, lane = threadIdx.x & 31;
    int h = w >> 2, pg = w & 3;
    int p0 = pg * 8;

    int img = img_ind[n];
    float px = obj_xy[n * 2 + 0];
    float py = obj_xy[n * 2 + 1];
    float st = strides[n];
    float qd = query[(size_t)n * EMBED + h * HD + lane];

    const float* kbase = g_key_t + (size_t)(img * NH + h) * HH * WW * HD;
    const float* vbase = g_val_t + (size_t)(img * NH + h) * HH * WW * HD;

    // ---- per-lane setup: lane i < 8 owns point p0+i ----
    int x0i = 0, y0i = 0;
    float wx = 0.f, wy = 0.f;
    if (lane < 8) {
        size_t obase = (size_t)n * 512 + h * 64 + (p0 + lane) * 2;
        float ox = g_off[obase + 0];
        float oy = g_off[obase + 1];
        float ixl = fmaf(px + ox * st, 0.25f, -0.5f);
        float iyl = fmaf(py + oy * st, 0.25f, -0.5f);
        float x0f = floorf(ixl), y0f = floorf(iyl);
        wx = ixl - x0f; wy = iyl - y0f;
        x0i = (int)x0f; y0i = (int)y0f;

        const float* x2d0 = x2d + (size_t)(img * 2 + 0) * HH * WW;
        const float* x2d1 = x2d + (size_t)(img * 2 + 1) * HH * WW;
        const float* mbase = x2d_mask + (size_t)img * HH * WW;
        float xa = 0.f, xb = 0.f, ms = 0.f;
#pragma unroll
        for (int c = 0; c < 4; c++) {
            int dx = c & 1, dy = c >> 1;
            float wgt = (dx ? wx : 1.f - wx) * (dy ? wy : 1.f - wy);
            int xi = x0i + dx, yi = y0i + dy;
            int pix = min(max(yi, 0), HH - 1) * WW + min(max(xi, 0), WW - 1);
            xa = fmaf(__ldg(&x2d0[pix]), wgt, xa);
            xb = fmaf(__ldg(&x2d1[pix]), wgt, xb);
            if ((xi >= 0) && (xi < WW) && (yi >= 0) && (yi < HH))
                ms = fmaf(__ldg(&mbase[pix]), wgt, ms);
        }
        sXa[h][p0 + lane] = xa;
        sXb[h][p0 + lane] = xb;
        sMask[h][p0 + lane] = ms;
    }

    // ---- K/V gather, 2 points per iteration, lane = channel d ----
    const float ascale = 0.17677669529663687f; // 1/sqrt(32)
#pragma unroll
    for (int i = 0; i < 8; i += 2) {
        int xA = __shfl_sync(0xffffffffu, x0i, i);
        int yA = __shfl_sync(0xffffffffu, y0i, i);
        float wxA = __shfl_sync(0xffffffffu, wx, i);
        float wyA = __shfl_sync(0xffffffffu, wy, i);
        int xB = __shfl_sync(0xffffffffu, x0i, i + 1);
        int yB = __shfl_sync(0xffffffffu, y0i, i + 1);
        float wxB = __shfl_sync(0xffffffffu, wx, i + 1);
        float wyB = __shfl_sync(0xffffffffu, wy, i + 1);

        float ksA = 0.f, vsA = 0.f, ksB = 0.f, vsB = 0.f;
#pragma unroll
        for (int c = 0; c < 4; c++) {
            int dx = c & 1, dy = c >> 1;
            float wgtA = (dx ? wxA : 1.f - wxA) * (dy ? wyA : 1.f - wyA);
            float wgtB = (dx ? wxB : 1.f - wxB) * (dy ? wyB : 1.f - wyB);
            int pixA = min(max(yA + dy, 0), HH - 1) * WW + min(max(xA + dx, 0), WW - 1);
            int pixB = min(max(yB + dy, 0), HH - 1) * WW + min(max(xB + dx, 0), WW - 1);
            float kA = kbase[(size_t)pixA * HD + lane];
            float vA = vbase[(size_t)pixA * HD + lane];
            float kB = kbase[(size_t)pixB * HD + lane];
            float vB = vbase[(size_t)pixB * HD + lane];
            ksA = fmaf(kA, wgtA, ksA);
            vsA = fmaf(vA, wgtA, vsA);
            ksB = fmaf(kB, wgtB, ksB);
            vsB = fmaf(vB, wgtB, vsB);
        }
        sV[h][p0 + i][lane] = vsA;
        sV[h][p0 + i + 1][lane] = vsB;

        float prtA = qd * ksA;
        float prtB = qd * ksB;
#pragma unroll
        for (int o = 16; o > 0; o >>= 1) {
            prtA += __shfl_xor_sync(0xffffffffu, prtA, o);
            prtB += __shfl_xor_sync(0xffffffffu, prtB, o);
        }
        if (lane == 0) {
            sA[h][p0 + i] = prtA * ascale;
            sA[h][p0 + i + 1] = prtB * ascale;
        }
    }
    __syncthreads();

    // ---- phase A: softmax + scalar outputs (warps 0-7); v_samples (16-31) --
    if (w < 8) {
        int hh = w;                    // lane = point p
        float a = sA[hh][lane];
        float msk = sMask[hh][lane];
        size_t sbase = (size_t)(n * NH + hh) * NP + lane;
        a_samples[sbase] = a;
        mask_samples[sbase] = msk;
        x2d_samples[(size_t)((n * NH + hh) * 2 + 0) * NP + lane] = sXa[hh][lane];
        x2d_samples[(size_t)((n * NH + hh) * 2 + 1) * NP + lane] = sXb[hh][lane];
        float m = a;
#pragma unroll
        for (int o = 16; o > 0; o >>= 1) m = fmaxf(m, __shfl_xor_sync(0xffffffffu, m, o));
        float e = expf(a - m);
        float s = e;
#pragma unroll
        for (int o = 16; o > 0; o >>= 1) s += __shfl_xor_sync(0xffffffffu, s, o);
        sSm[hh][lane] = e / s * msk;
    } else if (w >= 16) {
        int idx = w - 16;
        int hh = idx >> 1;
        int d0 = (idx & 1) * 16;       // lane = point p
#pragma unroll
        for (int d = 0; d < 16; d++)
            v_samples[(size_t)((n * NH + hh) * HD + d0 + d) * NP + lane] = sV[hh][lane][d0 + d];
    }
    __syncthreads();

    // ---- phase B: x0[h][d] = sum_p sm[p] * v[p][d]  (warps 8-15, lane = d) -
    if (w >= 8 && w < 16) {
        int hh = w - 8;
        float acc = 0.f;
#pragma unroll
        for (int p = 0; p < NP; p++)
            acc = fmaf(sSm[hh][p], sV[hh][p][lane], acc);
        x0_out[(size_t)n * EMBED + hh * HD + lane] = acc;
    }
}

// ---------------- launch ----------------------------------------------------
extern "C" void kernel_launch(void* const* d_in, const int* in_sizes, int n_in,
                              void* d_out, int out_size) {
    const float* query    = (const float*)d_in[0];
    const float* obj_emb  = (const float*)d_in[1];
    const float* key_feat = (const float*)d_in[2];
    const float* value    = (const float*)d_in[3];
    const float* x2d      = (const float*)d_in[4];
    const float* x2d_mask = (const float*)d_in[5];
    const float* obj_xy   = (const float*)d_in[6];
    const float* strides  = (const float*)d_in[7];
    const int*   img_ind  = (const int*)d_in[8];
    const float* w_off    = (const float*)d_in[9];
    const float* b_off    = (const float*)d_in[10];
    const float* w_out    = (const float*)d_in[11];
    const float* b_out    = (const float*)d_in[12];
    const float* ln1_g    = (const float*)d_in[13];
    const float* ln1_b    = (const float*)d_in[14];
    const float* w1       = (const float*)d_in[15];
    const float* b1       = (const float*)d_in[16];
    const float* w2       = (const float*)d_in[17];
    const float* b2       = (const float*)d_in[18];
    const float* ln2_g    = (const float*)d_in[19];
    const float* ln2_b    = (const float*)d_in[20];

    float* out = (float*)d_out;
    float* out_main = out;
    float* out_v    = out + (size_t)N_OBJ * EMBED;
    float* out_a    = out_v + (size_t)N_OBJ * NH * HD * NP;
    float* out_m    = out_a + (size_t)N_OBJ * NH * NP;
    float* out_x2d  = out_m + (size_t)N_OBJ * NH * NP;

    float *p_off, *p_x0, *p_x1, *p_hid;
    cudaGetSymbolAddress((void**)&p_off, g_off);
    cudaGetSymbolAddress((void**)&p_x0, g_x0);
    cudaGetSymbolAddress((void**)&p_x1, g_x1);
    cudaGetSymbolAddress((void**)&p_hid, g_hid);

    // 1) transpose K/V to (img,h,y,x,d)
    transpose_kv_kernel<<<dim3(WW / 32, HH, 2 * NUM_IMG * NH), dim3(32, 32)>>>(key_feat, value);

    // 2) offsets = obj_emb @ w_off + b_off   (2048x512, K=256)
    gemm_kernel<64><<<dim3(N_OBJ / 64, 8), 128>>>(obj_emb, w_off, b_off, nullptr,
                                                  p_off, EMBED, NH * NP * 2, 0);

    // 3) sampler
    sampler_kernel<<<N_OBJ, 1024>>>(query, obj_xy, strides, img_ind, x2d, x2d_mask,
                                    out_v, out_a, out_m, out_x2d, p_x0);

    // 4) x1 = LN1(x0 @ w_out + b_out + obj_emb)   (NC=256 -> BM=32 for blocks)
    gemm_kernel<32><<<dim3(N_OBJ / 32, 4), 128>>>(p_x0, w_out, b_out, obj_emb,
                                                  p_x1, EMBED, EMBED, EP_RESID);
    ln_kernel<<<N_OBJ / 8, 256>>>(p_x1, ln1_g, ln1_b);

    // 5) hid = relu(x1 @ w1 + b1)
    gemm_kernel<64><<<dim3(N_OBJ / 64, 16), 128>>>(p_x1, w1, b1, nullptr,
                                                   p_hid, EMBED, FFN, EP_RELU);

    // 6) out = LN2(hid @ w2 + b2 + x1)
    gemm_kernel<32><<<dim3(N_OBJ / 32, 4), 128>>>(p_hid, w2, b2, p_x1,
                                                  out_main, FFN, EMBED, EP_RESID);
    ln_kernel<<<N_OBJ / 8, 256>>>(out_main, ln2_g, ln2_b);
}